// round 6
// baseline (speedup 1.0000x reference)
#include <cuda_runtime.h>
#include <cuda_fp16.h>
#include <math.h>
#include <stdint.h>

#define BATCH 8
#define CI 512
#define CO 512
#define FH 50
#define FW 76
#define P 3800           // FH*FW
#define PPAD 3840        // padded pixels per image
#define NA 34200         // P*9
#define KD 4608          // CI*9
#define NSORT 65536
#define PRE 6000
#define POST 300

#define OFF_LOCS   0
#define OFF_SCORES 1094400   // 8*34200*4
#define OFF_ROIS   1641600   // + 8*34200*2
#define OFF_ANCH   1651200   // + 8*300*4

// ---------------- device scratch ----------------
__device__ float g_feat[BATCH*CO*P];
__device__ float g_fg[BATCH*NA];
__device__ float g_roi[BATCH*NA*4];
__device__ float g_key[BATCH*NSORT];
__device__ int   g_idx[BATCH*NSORT];

__device__ __align__(16) __half g_w1h[CO*KD];
__device__ __align__(16) __half g_w2h[CO*KD];
__device__ __align__(16) __half g_im1[(size_t)BATCH*PPAD*KD];
__device__ __align__(16) __half g_im2[(size_t)BATCH*PPAD*KD];

// ---------------- helpers ----------------
__device__ __forceinline__ uint32_t smem_u32(const void* p){
    uint32_t a;
    asm("{ .reg .u64 t; cvta.to.shared.u64 t, %1; cvt.u32.u64 %0, t; }" : "=r"(a) : "l"(p));
    return a;
}
#define CP16(dst, src)    asm volatile("cp.async.cg.shared.global [%0], [%1], 16;" :: "r"(dst), "l"(src))
#define CP_COMMIT()       asm volatile("cp.async.commit_group;" ::: "memory")
#define CP_WAIT2()        asm volatile("cp.async.wait_group 2;" ::: "memory")

#define MMA16816(d, a, b) asm volatile( \
    "mma.sync.aligned.m16n8k16.row.col.f32.f16.f16.f32 " \
    "{%0,%1,%2,%3}, {%4,%5,%6,%7}, {%8,%9}, {%0,%1,%2,%3};" \
    : "+f"((d)[0]), "+f"((d)[1]), "+f"((d)[2]), "+f"((d)[3]) \
    : "r"((a)[0]), "r"((a)[1]), "r"((a)[2]), "r"((a)[3]), \
      "r"((b)[0]), "r"((b)[1]))

#define LDSM4(r, a) asm volatile( \
    "ldmatrix.sync.aligned.m8n8.x4.shared.b16 {%0,%1,%2,%3}, [%4];" \
    : "=r"((r)[0]), "=r"((r)[1]), "=r"((r)[2]), "=r"((r)[3]) : "r"(a))

// ---------------- weight split (fp32 -> 2x fp16, hi/lo) ----------------
__global__ void wcvt_kernel(const float* __restrict__ w)
{
    int i = blockIdx.x*256 + threadIdx.x;
    if (i >= CO*KD) return;
    float v = w[i];
    __half h1 = __float2half_rn(v);
    float r = v - __half2float(h1);
    __half h2 = __float2half_rn(r * 4096.f);
    g_w1h[i] = h1; g_w2h[i] = h2;
}

// ---------------- im2col to fp16 x2 (K-contiguous rows per pixel) ----------------
__global__ __launch_bounds__(256) void im2col_kernel(const float* __restrict__ x)
{
    __shared__ float sx[32][3][78];
    int cg = blockIdx.x;     // 0..15 (32-ci group)
    int y  = blockIdx.y;     // 0..50 (row 50 = pad pixels)
    int n  = blockIdx.z;
    int tid = threadIdx.x;
    int ci0 = cg * 32;

    if (y == 50) {
        for (int i = tid; i < 40*288; i += 256) {
            int xx = i / 288, e = i % 288;
            size_t o = ((size_t)n*PPAD + 3800 + xx)*KD + cg*288 + e;
            g_im1[o] = __float2half(0.f);
            g_im2[o] = __float2half(0.f);
        }
        return;
    }
    for (int i = tid; i < 32*3*78; i += 256) ((float*)sx)[i] = 0.f;
    __syncthreads();
    const float* xn = x + ((size_t)n*CI + ci0)*(FH*FW);
    for (int i = tid; i < 32*3*76; i += 256) {
        int ci_l = i / 228, r = i % 228;
        int yy_l = r / 76, xx = r % 76;
        int yy = y + yy_l - 1;
        if (yy >= 0 && yy < FH)
            sx[ci_l][yy_l][xx+1] = xn[(size_t)ci_l*(FH*FW) + yy*FW + xx];
    }
    __syncthreads();
    for (int i = tid; i < 76*288; i += 256) {
        int xx = i / 288, e = i % 288;
        int ci_l = e / 9, r = e - ci_l*9;
        int ky = r / 3, kx = r - ky*3;
        float v = sx[ci_l][ky][xx + kx];
        __half h1 = __float2half_rn(v);
        float rr = v - __half2float(h1);
        __half h2 = __float2half_rn(rr * 4096.f);
        size_t o = ((size_t)n*PPAD + y*FW + xx)*KD + cg*288 + e;
        g_im1[o] = h1; g_im2[o] = h2;
    }
}

// ---------------- conv1 via mma.sync fp16x2 split (3 passes), ldmatrix loads ----------------
#define KC 32
#define NSTG 144              // KD / KC
#define STAGE_H 15360         // halves per stage: A1(5120) A2(5120) B1(2560) B2(2560)
#define SMEM_CONV (3*STAGE_H*2)

__global__ __launch_bounds__(256, 2) void conv_mma_kernel(const float* __restrict__ bias)
{
    extern __shared__ __half sh[];
    uint32_t sbase = smem_u32(sh);

    int tid  = threadIdx.x;
    int wid  = tid >> 5;
    int lane = tid & 31;
    int nimg = blockIdx.z;
    int co0  = blockIdx.x * 128;   // x fastest: co-blocks sharing B tile adjacent (L2)
    int px0  = blockIdx.y * 64;

    int wm = (wid & 3) * 32;       // warp M offset
    int wn = (wid >> 2) * 32;      // warp N offset
    int r0 = lane >> 2;

    float acc1[2][4][4], acc2[2][4][4];
#pragma unroll
    for (int mt = 0; mt < 2; ++mt)
#pragma unroll
        for (int nt = 0; nt < 4; ++nt)
#pragma unroll
            for (int c = 0; c < 4; ++c) { acc1[mt][nt][c] = 0.f; acc2[mt][nt][c] = 0.f; }

    const __half* w1b = g_w1h + (size_t)co0 * KD;
    const __half* w2b = g_w2h + (size_t)co0 * KD;
    const __half* i1b = g_im1 + ((size_t)nimg*PPAD + px0) * KD;
    const __half* i2b = g_im2 + ((size_t)nimg*PPAD + px0) * KD;

    // precomputed ldmatrix byte offsets (relative to stage base)
    int l15 = lane & 15;
    int lAc = (lane >> 4) * 8;          // A col offset (halves)
    int l7  = lane & 7;
    int lBc = ((lane >> 3) & 1) * 8;    // B col offset (halves)
    int lBr = (lane >> 4) * 8;          // B row offset (px)
    uint32_t aoff[2][2][2], boff[2][2][2];  // [split][mt|grp][ks]
#pragma unroll
    for (int sp = 0; sp < 2; ++sp)
#pragma unroll
        for (int mt = 0; mt < 2; ++mt)
#pragma unroll
            for (int ks = 0; ks < 2; ++ks)
                aoff[sp][mt][ks] = (uint32_t)((sp*5120 + (wm + mt*16 + l15)*40 + ks*16 + lAc) * 2);
#pragma unroll
    for (int sp = 0; sp < 2; ++sp)
#pragma unroll
        for (int g = 0; g < 2; ++g)
#pragma unroll
            for (int ks = 0; ks < 2; ++ks)
                boff[sp][g][ks] = (uint32_t)((10240 + sp*2560 + (wn + g*16 + l7 + lBr)*40 + ks*16 + lBc) * 2);

#define LOAD_STAGE(it, s) do { \
    int k0 = (it) * KC; \
    _Pragma("unroll") \
    for (int i = 0; i < 6; ++i) { \
        int c = tid + i*256; \
        uint32_t dsth; const __half* src; \
        if (c < 1024) { \
            int split = c >> 9, rc = c & 511, row = rc >> 2, ch = rc & 3; \
            dsth = (uint32_t)((s)*STAGE_H + split*5120 + row*40 + ch*8); \
            src = (split ? w2b : w1b) + (size_t)row*KD + k0 + ch*8; \
        } else { \
            int c2 = c - 1024, split = c2 >> 8, rc = c2 & 255, row = rc >> 2, ch = rc & 3; \
            dsth = (uint32_t)((s)*STAGE_H + 10240 + split*2560 + row*40 + ch*8); \
            src = (split ? i2b : i1b) + (size_t)row*KD + k0 + ch*8; \
        } \
        CP16(sbase + dsth*2, (const void*)src); \
    } \
    CP_COMMIT(); \
} while (0)

    LOAD_STAGE(0, 0);
    LOAD_STAGE(1, 1);
    LOAD_STAGE(2, 2);

    for (int it = 0; it < NSTG; ++it) {
        int s = it % 3;
        CP_WAIT2();
        __syncthreads();
        uint32_t stB = sbase + (uint32_t)(s * STAGE_H * 2);
#pragma unroll
        for (int ks = 0; ks < 2; ++ks) {
            uint32_t a1f[2][4], a2f[2][4], bt[4], b1f[4][2], b2f[4][2];
            LDSM4(a1f[0], stB + aoff[0][0][ks]);
            LDSM4(a1f[1], stB + aoff[0][1][ks]);
            LDSM4(a2f[0], stB + aoff[1][0][ks]);
            LDSM4(a2f[1], stB + aoff[1][1][ks]);
            LDSM4(bt, stB + boff[0][0][ks]);
            b1f[0][0]=bt[0]; b1f[0][1]=bt[1]; b1f[1][0]=bt[2]; b1f[1][1]=bt[3];
            LDSM4(bt, stB + boff[0][1][ks]);
            b1f[2][0]=bt[0]; b1f[2][1]=bt[1]; b1f[3][0]=bt[2]; b1f[3][1]=bt[3];
            LDSM4(bt, stB + boff[1][0][ks]);
            b2f[0][0]=bt[0]; b2f[0][1]=bt[1]; b2f[1][0]=bt[2]; b2f[1][1]=bt[3];
            LDSM4(bt, stB + boff[1][1][ks]);
            b2f[2][0]=bt[0]; b2f[2][1]=bt[1]; b2f[3][0]=bt[2]; b2f[3][1]=bt[3];
#pragma unroll
            for (int mt = 0; mt < 2; ++mt)
#pragma unroll
                for (int nt = 0; nt < 4; ++nt) {
                    MMA16816(acc1[mt][nt], a1f[mt], b1f[nt]);
                    MMA16816(acc2[mt][nt], a1f[mt], b2f[nt]);
                    MMA16816(acc2[mt][nt], a2f[mt], b1f[nt]);
                }
        }
        __syncthreads();
        if (it + 3 < NSTG) { LOAD_STAGE(it + 3, s); }
        else               { CP_COMMIT(); }
    }

    // epilogue: combine splits, stage in smem, coalesced global store
    __syncthreads();
    float* stg = (float*)sh;   // [128][66]
    const float inv = 1.f / 4096.f;
#pragma unroll
    for (int mt = 0; mt < 2; ++mt)
#pragma unroll
        for (int nt = 0; nt < 4; ++nt) {
            int row = wm + mt * 16 + r0;
            int col = wn + nt * 8 + (lane & 3) * 2;
            stg[ row      * 66 + col    ] = acc1[mt][nt][0] + acc2[mt][nt][0] * inv;
            stg[ row      * 66 + col + 1] = acc1[mt][nt][1] + acc2[mt][nt][1] * inv;
            stg[(row + 8) * 66 + col    ] = acc1[mt][nt][2] + acc2[mt][nt][2] * inv;
            stg[(row + 8) * 66 + col + 1] = acc1[mt][nt][3] + acc2[mt][nt][3] * inv;
        }
    __syncthreads();
    for (int e = tid; e < 128 * 64; e += 256) {
        int row = e >> 6, col = e & 63;
        int px = px0 + col;
        if (px < P) {
            float v = stg[row * 66 + col] + bias[co0 + row];
            g_feat[((size_t)nimg * CO + co0 + row) * P + px] = fmaxf(v, 0.f);
        }
    }
}

// ---------------- 1x1 heads (18 score + 36 loc) + softmax fg ----------------
__global__ __launch_bounds__(256) void heads_kernel(const float* __restrict__ sw,
                                                    const float* __restrict__ sbias,
                                                    const float* __restrict__ lw,
                                                    const float* __restrict__ lb,
                                                    float* __restrict__ out)
{
    extern __shared__ float ws[];   // [512][56]
    int n = blockIdx.y;
    int p = blockIdx.x * 256 + threadIdx.x;

    for (int e = threadIdx.x; e < 512*54; e += 256) {
        int ci = e / 54, ch = e - ci*54;
        ws[ci*56 + ch] = (ch < 18) ? sw[ch*512 + ci] : lw[(ch-18)*512 + ci];
    }
    __syncthreads();

    float acc[54];
#pragma unroll
    for (int c = 0; c < 54; ++c) acc[c] = 0.f;

    int pc = p < P ? p : P - 1;
    const float* f = g_feat + (size_t)n*CO*P + pc;
    for (int ci = 0; ci < 512; ++ci) {
        float fv = f[(size_t)ci*P];
        const float* wr = ws + ci*56;
#pragma unroll
        for (int ch = 0; ch < 54; ++ch) acc[ch] = fmaf(fv, wr[ch], acc[ch]);
    }

    if (p < P) {
        float* locs   = out + OFF_LOCS;
        float* scores = out + OFF_SCORES;
#pragma unroll
        for (int a = 0; a < 9; ++a) {
            float s0 = acc[a*2]   + sbias[a*2];
            float s1 = acc[a*2+1] + sbias[a*2+1];
            int i = n*NA + p*9 + a;
            scores[(size_t)i*2]   = s0;
            scores[(size_t)i*2+1] = s1;
            float m  = fmaxf(s0, s1);
            float e0 = expf(s0 - m), e1 = expf(s1 - m);
            g_fg[i] = e1 / (e0 + e1);
#pragma unroll
            for (int d = 0; d < 4; ++d)
                locs[(size_t)i*4 + d] = acc[18 + a*4 + d] + lb[a*4 + d];
        }
    }
}

// ---------------- anchors ----------------
__global__ void anchors_kernel(float* __restrict__ out)
{
    int i = blockIdx.x * 256 + threadIdx.x;
    if (i >= NA) return;
    int p = i / 9, a = i - p*9;
    int y = p / FW, x = p - y*FW;
    const float ratios[3] = {0.5f, 1.f, 2.f};
    const float scales[3] = {8.f, 16.f, 32.f};
    float r  = ratios[a/3];
    float sc = scales[a%3];
    float hh = 16.f * sc * sqrtf(r);
    float ww = 16.f * sc * sqrtf(1.f/r);
    float sx = x * 16.f, sy = y * 16.f;
    float* o = out + OFF_ANCH + (size_t)i*4;
    o[0] = sx + 8.f - ww*0.5f; o[1] = sy + 8.f - hh*0.5f;
    o[2] = sx + 8.f + ww*0.5f; o[3] = sy + 8.f + hh*0.5f;
}

// ---------------- loc2bbox + clip + min-size + sort keys ----------------
__device__ __forceinline__ float read_dim(const void* p)
{
    int v = *(const int*)p;
    if (v > 0 && v < 100000) return (float)v;
    return __int_as_float(v);
}

__global__ void prep_kernel(const float* __restrict__ out,
                            const void* __restrict__ ihp,
                            const void* __restrict__ iwp)
{
    int t = blockIdx.x * 256 + threadIdx.x;
    int n = t >> 16;
    int i = t & (NSORT - 1);
    if (n >= BATCH) return;
    if (i < NA) {
        const float* anc = out + OFF_ANCH + (size_t)i*4;
        const float* loc = out + OFF_LOCS + ((size_t)n*NA + i)*4;
        float a0 = anc[0], a1 = anc[1], a2 = anc[2], a3 = anc[3];
        float aw = a2 - a0, ah = a3 - a1;
        float ax = a0 + 0.5f*aw, ay = a1 + 0.5f*ah;
        float cx = loc[0]*aw + ax;
        float cy = loc[1]*ah + ay;
        float wb = expf(loc[2])*aw;
        float hb = expf(loc[3])*ah;
        float IW = read_dim(iwp), IH = read_dim(ihp);
        float x1 = fminf(fmaxf(cx - 0.5f*wb, 0.f), IW);
        float y1 = fminf(fmaxf(cy - 0.5f*hb, 0.f), IH);
        float x2 = fminf(fmaxf(cx + 0.5f*wb, 0.f), IW);
        float y2 = fminf(fmaxf(cy + 0.5f*hb, 0.f), IH);
        float* rr = g_roi + ((size_t)n*NA + i)*4;
        rr[0] = x1; rr[1] = y1; rr[2] = x2; rr[3] = y2;
        bool valid = ((x2 - x1) >= 16.f) && ((y2 - y1) >= 16.f);
        g_key[n*NSORT + i] = valid ? g_fg[n*NA + i] : -INFINITY;
    } else {
        g_key[n*NSORT + i] = -INFINITY;
    }
    g_idx[n*NSORT + i] = i;
}

// ---------------- bitonic sort ----------------
__device__ __forceinline__ bool sbefore(float ka, int ia, float kb, int ib)
{
    if (ka > kb) return true;
    if (ka < kb) return false;
    return ia < ib;
}

__global__ __launch_bounds__(1024) void bitonic_local(void)
{
    __shared__ float sk[2048];
    __shared__ int   si[2048];
    int base = blockIdx.x * 2048;
    int t = threadIdx.x;
    sk[t] = g_key[base+t]; si[t] = g_idx[base+t];
    sk[t+1024] = g_key[base+t+1024]; si[t+1024] = g_idx[base+t+1024];
    __syncthreads();
    for (int k = 2; k <= 2048; k <<= 1) {
        for (int j = k >> 1; j >= 1; j >>= 1) {
            int i1 = ((t & ~(j-1)) << 1) | (t & (j-1));
            int i2 = i1 + j;
            bool up = ((((base+i1) & (NSORT-1)) & k) == 0);
            float ka = sk[i1], kb = sk[i2];
            int ia = si[i1], ib = si[i2];
            if (sbefore(ka, ia, kb, ib) != up) {
                sk[i1] = kb; si[i1] = ib; sk[i2] = ka; si[i2] = ia;
            }
            __syncthreads();
        }
    }
    g_key[base+t] = sk[t]; g_idx[base+t] = si[t];
    g_key[base+t+1024] = sk[t+1024]; g_idx[base+t+1024] = si[t+1024];
}

__global__ __launch_bounds__(256) void bitonic_global(int j, int k)
{
    int t = blockIdx.x * 256 + threadIdx.x;
    int i1 = ((t & ~(j-1)) << 1) | (t & (j-1));
    int i2 = i1 + j;
    bool up = (((i1 & (NSORT-1)) & k) == 0);
    float ka = g_key[i1], kb = g_key[i2];
    int ia = g_idx[i1], ib = g_idx[i2];
    if (sbefore(ka, ia, kb, ib) != up) {
        g_key[i1] = kb; g_idx[i1] = ib; g_key[i2] = ka; g_idx[i2] = ia;
    }
}

__global__ __launch_bounds__(1024) void bitonic_merge_local(int k)
{
    __shared__ float sk[2048];
    __shared__ int   si[2048];
    int base = blockIdx.x * 2048;
    int t = threadIdx.x;
    sk[t] = g_key[base+t]; si[t] = g_idx[base+t];
    sk[t+1024] = g_key[base+t+1024]; si[t+1024] = g_idx[base+t+1024];
    __syncthreads();
    for (int j = 1024; j >= 1; j >>= 1) {
        int i1 = ((t & ~(j-1)) << 1) | (t & (j-1));
        int i2 = i1 + j;
        bool up = ((((base+i1) & (NSORT-1)) & k) == 0);
        float ka = sk[i1], kb = sk[i2];
        int ia = si[i1], ib = si[i2];
        if (sbefore(ka, ia, kb, ib) != up) {
            sk[i1] = kb; si[i1] = ib; sk[i2] = ka; si[i2] = ia;
        }
        __syncthreads();
    }
    g_key[base+t] = sk[t]; g_idx[base+t] = si[t];
    g_key[base+t+1024] = sk[t+1024]; g_idx[base+t+1024] = si[t+1024];
}

// ---------------- greedy NMS (exact, two-level chunked) + top-300 ----------------
__device__ __forceinline__ bool iou_gt(float ax1, float ay1, float ax2, float ay2, float aa,
                                       float bx1, float by1, float bx2, float by2, float ba)
{
    float ix1 = fmaxf(ax1, bx1);
    float iy1 = fmaxf(ay1, by1);
    float ix2 = fminf(ax2, bx2);
    float iy2 = fminf(ay2, by2);
    float inter = fmaxf(ix2 - ix1, 0.f) * fmaxf(iy2 - iy1, 0.f);
    float iou = inter / (aa + ba - inter + 1e-9f);
    return iou > 0.7f;
}

__global__ __launch_bounds__(1024) void nms_kernel(float* __restrict__ out)
{
    extern __shared__ float sm[];
    float* x1 = sm;
    float* y1 = sm + PRE;
    float* x2 = sm + 2*PRE;
    float* y2 = sm + 3*PRE;
    float* ar = sm + 4*PRE;
    unsigned char* keep = (unsigned char*)(sm + 5*PRE);
    __shared__ unsigned long long msk[64];
    __shared__ int kidx[64];
    __shared__ int kcnt;
    __shared__ int wsum[32];

    int n = blockIdx.x;
    int t = threadIdx.x;

    for (int i = t; i < PRE; i += 1024) {
        float k = g_key[n*NSORT + i];
        if (isfinite(k)) {
            int id = g_idx[n*NSORT + i];
            const float* r = g_roi + ((size_t)n*NA + id)*4;
            x1[i] = r[0]; y1[i] = r[1]; x2[i] = r[2]; y2[i] = r[3];
            ar[i] = (r[2]-r[0])*(r[3]-r[1]);
            keep[i] = 1;
        } else {
            x1[i] = y1[i] = x2[i] = y2[i] = ar[i] = 0.f;
            keep[i] = 0;
        }
    }
    for (int e = t; e < POST*4; e += 1024)
        out[OFF_ROIS + n*POST*4 + e] = 0.f;
    __syncthreads();

    for (int c0 = 0; c0 < PRE; c0 += 64) {
        int cend = c0 + 64 < PRE ? c0 + 64 : PRE;
        int cn = cend - c0;

        // phase 1a: per-box suppression masks within chunk (threads 0..63)
        if (t < 64) {
            unsigned long long m = 0ull;
            if (t < cn && keep[c0 + t]) {
                float bx1 = x1[c0+t], by1 = y1[c0+t], bx2 = x2[c0+t], by2 = y2[c0+t], ba = ar[c0+t];
                for (int k = t + 1; k < cn; ++k) {
                    if (iou_gt(bx1, by1, bx2, by2, ba,
                               x1[c0+k], y1[c0+k], x2[c0+k], y2[c0+k], ar[c0+k]))
                        m |= 1ull << k;
                }
            }
            msk[t] = m;
        }
        __syncthreads();

        // phase 1b: serial greedy resolve within chunk (warp 0, register dance)
        if (t < 32) {
            unsigned long long m0 = msk[t], m1 = msk[t + 32];
            unsigned b0 = __ballot_sync(0xffffffffu, (t < cn) && keep[c0 + t]);
            unsigned b1 = __ballot_sync(0xffffffffu, (t + 32 < cn) && keep[c0 + t + 32]);
            unsigned long long kmask = (unsigned long long)b0 | ((unsigned long long)b1 << 32);
            unsigned long long rm = 0ull, fk = 0ull;
            for (int k = 0; k < cn; ++k) {
                bool kp = ((kmask >> k) & 1ull) && !((rm >> k) & 1ull);
                if (kp) {
                    fk |= 1ull << k;
                    unsigned long long src = (k < 32) ? m0 : m1;
                    unsigned lo = __shfl_sync(0xffffffffu, (unsigned)src, k & 31);
                    unsigned hi = __shfl_sync(0xffffffffu, (unsigned)(src >> 32), k & 31);
                    rm |= ((unsigned long long)hi << 32) | lo;
                }
            }
            if (t < cn) {
                bool kp = (fk >> t) & 1ull;
                keep[c0 + t] = kp;
                if (kp) kidx[__popcll(fk & ((1ull << t) - 1ull))] = c0 + t;
            }
            if (t + 32 < cn) {
                bool kp = (fk >> (t + 32)) & 1ull;
                keep[c0 + t + 32] = kp;
                if (kp) kidx[__popcll(fk & ((1ull << (t + 32)) - 1ull))] = c0 + t + 32;
            }
            if (t == 0) kcnt = (int)__popcll(fk);
        }
        __syncthreads();

        // phase 2: apply chunk's kept boxes to all later boxes
        int kc = kcnt;
        if (kc > 0) {
            for (int j = cend + t; j < PRE; j += 1024) {
                if (keep[j]) {
                    float jx1 = x1[j], jy1 = y1[j], jx2 = x2[j], jy2 = y2[j], ja = ar[j];
                    for (int q = 0; q < kc; ++q) {
                        int i = kidx[q];
                        if (iou_gt(x1[i], y1[i], x2[i], y2[i], ar[i],
                                   jx1, jy1, jx2, jy2, ja)) { keep[j] = 0; break; }
                    }
                }
            }
        }
        __syncthreads();
    }

    // stable compaction: first POST kept boxes in score order
    int base_i = t * 6;
    int loc[6];
    int lsum = 0;
#pragma unroll
    for (int q = 0; q < 6; ++q) {
        int ii = base_i + q;
        int v = (ii < PRE) ? (int)keep[ii] : 0;
        loc[q] = lsum;
        lsum += v;
    }
    int lane = t & 31, wid = t >> 5;
    int v = lsum;
    for (int o = 1; o < 32; o <<= 1) {
        int u = __shfl_up_sync(0xffffffffu, v, o);
        if (lane >= o) v += u;
    }
    if (lane == 31) wsum[wid] = v;
    __syncthreads();
    if (wid == 0) {
        int w2 = wsum[lane];
        for (int o = 1; o < 32; o <<= 1) {
            int u = __shfl_up_sync(0xffffffffu, w2, o);
            if (lane >= o) w2 += u;
        }
        wsum[lane] = w2;
    }
    __syncthreads();
    int excl = v - lsum + (wid > 0 ? wsum[wid-1] : 0);
#pragma unroll
    for (int q = 0; q < 6; ++q) {
        int ii = base_i + q;
        if (ii < PRE && keep[ii]) {
            int r = excl + loc[q];
            if (r < POST) {
                float* o = out + OFF_ROIS + ((size_t)n*POST + r)*4;
                o[0] = x1[ii]; o[1] = y1[ii]; o[2] = x2[ii]; o[3] = y2[ii];
            }
        }
    }
}

// ---------------- launch ----------------
extern "C" void kernel_launch(void* const* d_in, const int* in_sizes, int n_in,
                              void* d_out, int out_size)
{
    const float* x   = (const float*)d_in[0];
    const float* w1  = (const float*)d_in[1];
    const float* bc  = (const float*)d_in[2];
    const float* sw  = (const float*)d_in[3];
    const float* sbb = (const float*)d_in[4];
    const float* lw  = (const float*)d_in[5];
    const float* lb  = (const float*)d_in[6];
    const void*  ih  = d_in[7];
    const void*  iw  = d_in[8];
    float* out = (float*)d_out;

    static bool attr_done = false;
    if (!attr_done) {
        cudaFuncSetAttribute(conv_mma_kernel, cudaFuncAttributeMaxDynamicSharedMemorySize, SMEM_CONV);
        cudaFuncSetAttribute(heads_kernel, cudaFuncAttributeMaxDynamicSharedMemorySize, 512*56*4);
        cudaFuncSetAttribute(nms_kernel, cudaFuncAttributeMaxDynamicSharedMemorySize, 131072);
        attr_done = true;
    }

    wcvt_kernel<<<(CO*KD + 255)/256, 256>>>(w1);
    im2col_kernel<<<dim3(16, 51, BATCH), 256>>>(x);
    anchors_kernel<<<(NA + 255)/256, 256>>>(out);
    conv_mma_kernel<<<dim3(CO/128, PPAD/64, BATCH), 256, SMEM_CONV>>>(bc);
    heads_kernel<<<dim3((P + 255)/256, BATCH), 256, 512*56*4>>>(sw, sbb, lw, lb, out);
    prep_kernel<<<(BATCH*NSORT)/256, 256>>>(out, ih, iw);

    bitonic_local<<<BATCH*NSORT/2048, 1024>>>();
    for (int k = 4096; k <= NSORT; k <<= 1) {
        for (int j = k >> 1; j >= 2048; j >>= 1)
            bitonic_global<<<(BATCH*NSORT/2)/256, 256>>>(j, k);
        bitonic_merge_local<<<BATCH*NSORT/2048, 1024>>>(k);
    }

    nms_kernel<<<BATCH, 1024, 5*PRE*4 + PRE>>>(out);
}

// round 7
// speedup vs baseline: 1.0497x; 1.0497x over previous
#include <cuda_runtime.h>
#include <cuda_fp16.h>
#include <math.h>
#include <stdint.h>

#define BATCH 8
#define CI 512
#define CO 512
#define FH 50
#define FW 76
#define P 3800           // FH*FW
#define PPAD 3840        // padded pixels per image
#define NA 34200         // P*9
#define KD 4608          // CI*9
#define NSORT 65536
#define PRE 6000
#define POST 300

#define OFF_LOCS   0
#define OFF_SCORES 1094400   // 8*34200*4
#define OFF_ROIS   1641600   // + 8*34200*2
#define OFF_ANCH   1651200   // + 8*300*4

// ---------------- device scratch ----------------
__device__ float g_feat[BATCH*CO*P];
__device__ float g_fg[BATCH*NA];
__device__ float g_roi[BATCH*NA*4];
__device__ float g_key[BATCH*NSORT];
__device__ int   g_idx[BATCH*NSORT];

__device__ __align__(16) __half g_w1h[CO*KD];
__device__ __align__(16) __half g_w2h[CO*KD];
__device__ __align__(16) __half g_im1[(size_t)BATCH*PPAD*KD];
__device__ __align__(16) __half g_im2[(size_t)BATCH*PPAD*KD];

// ---------------- helpers ----------------
__device__ __forceinline__ uint32_t smem_u32(const void* p){
    uint32_t a;
    asm("{ .reg .u64 t; cvta.to.shared.u64 t, %1; cvt.u32.u64 %0, t; }" : "=r"(a) : "l"(p));
    return a;
}
#define CP16(dst, src)    asm volatile("cp.async.cg.shared.global [%0], [%1], 16;" :: "r"(dst), "l"(src))
#define CP_COMMIT()       asm volatile("cp.async.commit_group;" ::: "memory")
#define CP_WAIT1()        asm volatile("cp.async.wait_group 1;" ::: "memory")

#define MMA16816(d, a, b) asm volatile( \
    "mma.sync.aligned.m16n8k16.row.col.f32.f16.f16.f32 " \
    "{%0,%1,%2,%3}, {%4,%5,%6,%7}, {%8,%9}, {%0,%1,%2,%3};" \
    : "+f"((d)[0]), "+f"((d)[1]), "+f"((d)[2]), "+f"((d)[3]) \
    : "r"((a)[0]), "r"((a)[1]), "r"((a)[2]), "r"((a)[3]), \
      "r"((b)[0]), "r"((b)[1]))

#define LDSM4(r, a) asm volatile( \
    "ldmatrix.sync.aligned.m8n8.x4.shared.b16 {%0,%1,%2,%3}, [%4];" \
    : "=r"((r)[0]), "=r"((r)[1]), "=r"((r)[2]), "=r"((r)[3]) : "r"(a))

// ---------------- weight split (fp32 -> 2x fp16, hi/lo) ----------------
__global__ void wcvt_kernel(const float* __restrict__ w)
{
    int i = blockIdx.x*256 + threadIdx.x;
    if (i >= CO*KD) return;
    float v = w[i];
    __half h1 = __float2half_rn(v);
    float r = v - __half2float(h1);
    __half h2 = __float2half_rn(r * 4096.f);
    g_w1h[i] = h1; g_w2h[i] = h2;
}

// ---------------- im2col to fp16 x2 (vectorized 16B stores) ----------------
__global__ __launch_bounds__(256) void im2col_kernel(const float* __restrict__ x)
{
    __shared__ float sx[32][3][78];
    int cg = blockIdx.x;     // 0..15 (32-ci group)
    int y  = blockIdx.y;     // 0..50 (row 50 = pad pixels)
    int n  = blockIdx.z;
    int tid = threadIdx.x;
    int ci0 = cg * 32;

    if (y == 50) {
        uint4 z = make_uint4(0, 0, 0, 0);
        for (int i = tid; i < 40*36; i += 256) {
            int xx = i / 36, c = i % 36;
            size_t o = ((size_t)n*PPAD + 3800 + xx)*KD + cg*288 + c*8;
            *(uint4*)(g_im1 + o) = z;
            *(uint4*)(g_im2 + o) = z;
        }
        return;
    }
    for (int i = tid; i < 32*3*78; i += 256) ((float*)sx)[i] = 0.f;
    __syncthreads();
    const float* xn = x + ((size_t)n*CI + ci0)*(FH*FW);
    for (int i = tid; i < 32*3*76; i += 256) {
        int ci_l = i / 228, r = i % 228;
        int yy_l = r / 76, xx = r % 76;
        int yy = y + yy_l - 1;
        if (yy >= 0 && yy < FH)
            sx[ci_l][yy_l][xx+1] = xn[(size_t)ci_l*(FH*FW) + yy*FW + xx];
    }
    __syncthreads();
    for (int i = tid; i < 76*36; i += 256) {
        int xx = i / 36, c = i % 36;
        int e0 = c * 8;
        __half h1v[8], h2v[8];
#pragma unroll
        for (int q = 0; q < 8; ++q) {
            int e = e0 + q;
            int ci_l = e / 9, r = e - ci_l*9;
            int ky = r / 3, kx = r - ky*3;
            float v = sx[ci_l][ky][xx + kx];
            __half h1 = __float2half_rn(v);
            float rr = v - __half2float(h1);
            h1v[q] = h1;
            h2v[q] = __float2half_rn(rr * 4096.f);
        }
        size_t o = ((size_t)n*PPAD + y*FW + xx)*KD + cg*288 + e0;
        *(uint4*)(g_im1 + o) = *(const uint4*)h1v;
        *(uint4*)(g_im2 + o) = *(const uint4*)h2v;
    }
}

// ---------------- conv1 via mma.sync fp16x2 split, KC=64, 2-stage ----------------
#define KC 64
#define NSTG 72               // KD / KC
#define A_SP 9216             // halves per A split: 128 rows x 72
#define B_SP 4608             // halves per B split: 64 rows x 72
#define STAGE_H 27648         // A1 A2 B1 B2
#define SMEM_CONV (2*STAGE_H*2)   // 110592 B

__global__ __launch_bounds__(256, 2) void conv_mma_kernel(const float* __restrict__ bias)
{
    extern __shared__ __half sh[];
    uint32_t sbase = smem_u32(sh);

    int tid  = threadIdx.x;
    int wid  = tid >> 5;
    int lane = tid & 31;
    int nimg = blockIdx.z;
    int co0  = blockIdx.x * 128;   // x fastest: co-blocks sharing B tile adjacent (L2)
    int px0  = blockIdx.y * 64;

    int wm = (wid & 3) * 32;       // warp M offset
    int wn = (wid >> 2) * 32;      // warp N offset
    int r0 = lane >> 2;

    float acc1[2][4][4], acc2[2][4][4];
#pragma unroll
    for (int mt = 0; mt < 2; ++mt)
#pragma unroll
        for (int nt = 0; nt < 4; ++nt)
#pragma unroll
            for (int c = 0; c < 4; ++c) { acc1[mt][nt][c] = 0.f; acc2[mt][nt][c] = 0.f; }

    const __half* w1b = g_w1h + (size_t)co0 * KD;
    const __half* w2b = g_w2h + (size_t)co0 * KD;
    const __half* i1b = g_im1 + ((size_t)nimg*PPAD + px0) * KD;
    const __half* i2b = g_im2 + ((size_t)nimg*PPAD + px0) * KD;

    // precomputed ldmatrix byte offsets (relative to stage base), ks adds 32B
    int l15 = lane & 15;
    int lAc = (lane >> 4) * 8;          // A col offset (halves)
    int l7  = lane & 7;
    int lBc = ((lane >> 3) & 1) * 8;    // B col offset (halves)
    int lBr = (lane >> 4) * 8;          // B row offset (px)
    uint32_t aoff[2][2], boff[2][2];    // [split][mt|grp]
#pragma unroll
    for (int sp = 0; sp < 2; ++sp)
#pragma unroll
        for (int mt = 0; mt < 2; ++mt)
            aoff[sp][mt] = (uint32_t)((sp*A_SP + (wm + mt*16 + l15)*72 + lAc) * 2);
#pragma unroll
    for (int sp = 0; sp < 2; ++sp)
#pragma unroll
        for (int g = 0; g < 2; ++g)
            boff[sp][g] = (uint32_t)((2*A_SP + sp*B_SP + (wn + g*16 + l7 + lBr)*72 + lBc) * 2);

#define LOAD_STAGE(it, s) do { \
    int k0 = (it) * KC; \
    _Pragma("unroll") \
    for (int i = 0; i < 12; ++i) { \
        int c = tid + i*256; \
        uint32_t dsth; const __half* src; \
        if (c < 2048) { \
            int split = c >> 10, rc = c & 1023, row = rc >> 3, ch = rc & 7; \
            dsth = (uint32_t)((s)*STAGE_H + split*A_SP + row*72 + ch*8); \
            src = (split ? w2b : w1b) + (size_t)row*KD + k0 + ch*8; \
        } else { \
            int c2 = c - 2048, split = c2 >> 9, rc = c2 & 511, row = rc >> 3, ch = rc & 7; \
            dsth = (uint32_t)((s)*STAGE_H + 2*A_SP + split*B_SP + row*72 + ch*8); \
            src = (split ? i2b : i1b) + (size_t)row*KD + k0 + ch*8; \
        } \
        CP16(sbase + dsth*2, (const void*)src); \
    } \
    CP_COMMIT(); \
} while (0)

    LOAD_STAGE(0, 0);
    LOAD_STAGE(1, 1);

    for (int it = 0; it < NSTG; ++it) {
        int s = it & 1;
        CP_WAIT1();
        __syncthreads();
        uint32_t stB = sbase + (uint32_t)(s * STAGE_H * 2);
#pragma unroll
        for (int ks = 0; ks < 4; ++ks) {
            uint32_t ko = (uint32_t)(ks * 32);
            uint32_t a1f[2][4], a2f[2][4], bt[4], b1f[4][2], b2f[4][2];
            LDSM4(a1f[0], stB + aoff[0][0] + ko);
            LDSM4(a1f[1], stB + aoff[0][1] + ko);
            LDSM4(a2f[0], stB + aoff[1][0] + ko);
            LDSM4(a2f[1], stB + aoff[1][1] + ko);
            LDSM4(bt, stB + boff[0][0] + ko);
            b1f[0][0]=bt[0]; b1f[0][1]=bt[1]; b1f[1][0]=bt[2]; b1f[1][1]=bt[3];
            LDSM4(bt, stB + boff[0][1] + ko);
            b1f[2][0]=bt[0]; b1f[2][1]=bt[1]; b1f[3][0]=bt[2]; b1f[3][1]=bt[3];
            LDSM4(bt, stB + boff[1][0] + ko);
            b2f[0][0]=bt[0]; b2f[0][1]=bt[1]; b2f[1][0]=bt[2]; b2f[1][1]=bt[3];
            LDSM4(bt, stB + boff[1][1] + ko);
            b2f[2][0]=bt[0]; b2f[2][1]=bt[1]; b2f[3][0]=bt[2]; b2f[3][1]=bt[3];
#pragma unroll
            for (int mt = 0; mt < 2; ++mt)
#pragma unroll
                for (int nt = 0; nt < 4; ++nt) {
                    MMA16816(acc1[mt][nt], a1f[mt], b1f[nt]);
                    MMA16816(acc2[mt][nt], a1f[mt], b2f[nt]);
                    MMA16816(acc2[mt][nt], a2f[mt], b1f[nt]);
                }
        }
        __syncthreads();
        if (it + 2 < NSTG) { LOAD_STAGE(it + 2, s); }
        else               { CP_COMMIT(); }
    }

    // epilogue: combine splits, stage in smem, coalesced global store
    __syncthreads();
    float* stg = (float*)sh;   // [128][66]
    const float inv = 1.f / 4096.f;
#pragma unroll
    for (int mt = 0; mt < 2; ++mt)
#pragma unroll
        for (int nt = 0; nt < 4; ++nt) {
            int row = wm + mt * 16 + r0;
            int col = wn + nt * 8 + (lane & 3) * 2;
            stg[ row      * 66 + col    ] = acc1[mt][nt][0] + acc2[mt][nt][0] * inv;
            stg[ row      * 66 + col + 1] = acc1[mt][nt][1] + acc2[mt][nt][1] * inv;
            stg[(row + 8) * 66 + col    ] = acc1[mt][nt][2] + acc2[mt][nt][2] * inv;
            stg[(row + 8) * 66 + col + 1] = acc1[mt][nt][3] + acc2[mt][nt][3] * inv;
        }
    __syncthreads();
    for (int e = tid; e < 128 * 64; e += 256) {
        int row = e >> 6, col = e & 63;
        int px = px0 + col;
        if (px < P) {
            float v = stg[row * 66 + col] + bias[co0 + row];
            g_feat[((size_t)nimg * CO + co0 + row) * P + px] = fmaxf(v, 0.f);
        }
    }
}

// ---------------- 1x1 heads (18 score + 36 loc) + softmax fg ----------------
__global__ __launch_bounds__(256) void heads_kernel(const float* __restrict__ sw,
                                                    const float* __restrict__ sbias,
                                                    const float* __restrict__ lw,
                                                    const float* __restrict__ lb,
                                                    float* __restrict__ out)
{
    extern __shared__ float ws[];   // [512][54]
    int n = blockIdx.y;
    int p = blockIdx.x * 256 + threadIdx.x;

    for (int e = threadIdx.x; e < 512*54; e += 256) {
        int ci = e / 54, ch = e - ci*54;
        ws[e] = (ch < 18) ? sw[ch*512 + ci] : lw[(ch-18)*512 + ci];
    }
    __syncthreads();

    float acc[54];
#pragma unroll
    for (int c = 0; c < 54; ++c) acc[c] = 0.f;

    int pc = p < P ? p : P - 1;
    const float* f = g_feat + (size_t)n*CO*P + pc;
    for (int ci = 0; ci < 512; ++ci) {
        float fv = f[(size_t)ci*P];
        const float* wr = ws + ci*54;
#pragma unroll
        for (int ch = 0; ch < 54; ++ch) acc[ch] = fmaf(fv, wr[ch], acc[ch]);
    }

    if (p < P) {
        float* locs   = out + OFF_LOCS;
        float* scores = out + OFF_SCORES;
#pragma unroll
        for (int a = 0; a < 9; ++a) {
            float s0 = acc[a*2]   + sbias[a*2];
            float s1 = acc[a*2+1] + sbias[a*2+1];
            int i = n*NA + p*9 + a;
            scores[(size_t)i*2]   = s0;
            scores[(size_t)i*2+1] = s1;
            float m  = fmaxf(s0, s1);
            float e0 = expf(s0 - m), e1 = expf(s1 - m);
            g_fg[i] = e1 / (e0 + e1);
#pragma unroll
            for (int d = 0; d < 4; ++d)
                locs[(size_t)i*4 + d] = acc[18 + a*4 + d] + lb[a*4 + d];
        }
    }
}

// ---------------- anchors ----------------
__global__ void anchors_kernel(float* __restrict__ out)
{
    int i = blockIdx.x * 256 + threadIdx.x;
    if (i >= NA) return;
    int p = i / 9, a = i - p*9;
    int y = p / FW, x = p - y*FW;
    const float ratios[3] = {0.5f, 1.f, 2.f};
    const float scales[3] = {8.f, 16.f, 32.f};
    float r  = ratios[a/3];
    float sc = scales[a%3];
    float hh = 16.f * sc * sqrtf(r);
    float ww = 16.f * sc * sqrtf(1.f/r);
    float sx = x * 16.f, sy = y * 16.f;
    float* o = out + OFF_ANCH + (size_t)i*4;
    o[0] = sx + 8.f - ww*0.5f; o[1] = sy + 8.f - hh*0.5f;
    o[2] = sx + 8.f + ww*0.5f; o[3] = sy + 8.f + hh*0.5f;
}

// ---------------- loc2bbox + clip + min-size + sort keys ----------------
__device__ __forceinline__ float read_dim(const void* p)
{
    int v = *(const int*)p;
    if (v > 0 && v < 100000) return (float)v;
    return __int_as_float(v);
}

__global__ void prep_kernel(const float* __restrict__ out,
                            const void* __restrict__ ihp,
                            const void* __restrict__ iwp)
{
    int t = blockIdx.x * 256 + threadIdx.x;
    int n = t >> 16;
    int i = t & (NSORT - 1);
    if (n >= BATCH) return;
    if (i < NA) {
        const float* anc = out + OFF_ANCH + (size_t)i*4;
        const float* loc = out + OFF_LOCS + ((size_t)n*NA + i)*4;
        float a0 = anc[0], a1 = anc[1], a2 = anc[2], a3 = anc[3];
        float aw = a2 - a0, ah = a3 - a1;
        float ax = a0 + 0.5f*aw, ay = a1 + 0.5f*ah;
        float cx = loc[0]*aw + ax;
        float cy = loc[1]*ah + ay;
        float wb = expf(loc[2])*aw;
        float hb = expf(loc[3])*ah;
        float IW = read_dim(iwp), IH = read_dim(ihp);
        float x1 = fminf(fmaxf(cx - 0.5f*wb, 0.f), IW);
        float y1 = fminf(fmaxf(cy - 0.5f*hb, 0.f), IH);
        float x2 = fminf(fmaxf(cx + 0.5f*wb, 0.f), IW);
        float y2 = fminf(fmaxf(cy + 0.5f*hb, 0.f), IH);
        float* rr = g_roi + ((size_t)n*NA + i)*4;
        rr[0] = x1; rr[1] = y1; rr[2] = x2; rr[3] = y2;
        bool valid = ((x2 - x1) >= 16.f) && ((y2 - y1) >= 16.f);
        g_key[n*NSORT + i] = valid ? g_fg[n*NA + i] : -INFINITY;
    } else {
        g_key[n*NSORT + i] = -INFINITY;
    }
    g_idx[n*NSORT + i] = i;
}

// ---------------- bitonic sort ----------------
__device__ __forceinline__ bool sbefore(float ka, int ia, float kb, int ib)
{
    if (ka > kb) return true;
    if (ka < kb) return false;
    return ia < ib;
}

__global__ __launch_bounds__(1024) void bitonic_local(void)
{
    __shared__ float sk[2048];
    __shared__ int   si[2048];
    int base = blockIdx.x * 2048;
    int t = threadIdx.x;
    sk[t] = g_key[base+t]; si[t] = g_idx[base+t];
    sk[t+1024] = g_key[base+t+1024]; si[t+1024] = g_idx[base+t+1024];
    __syncthreads();
    for (int k = 2; k <= 2048; k <<= 1) {
        for (int j = k >> 1; j >= 1; j >>= 1) {
            int i1 = ((t & ~(j-1)) << 1) | (t & (j-1));
            int i2 = i1 + j;
            bool up = ((((base+i1) & (NSORT-1)) & k) == 0);
            float ka = sk[i1], kb = sk[i2];
            int ia = si[i1], ib = si[i2];
            if (sbefore(ka, ia, kb, ib) != up) {
                sk[i1] = kb; si[i1] = ib; sk[i2] = ka; si[i2] = ia;
            }
            __syncthreads();
        }
    }
    g_key[base+t] = sk[t]; g_idx[base+t] = si[t];
    g_key[base+t+1024] = sk[t+1024]; g_idx[base+t+1024] = si[t+1024];
}

__global__ __launch_bounds__(256) void bitonic_global(int j, int k)
{
    int t = blockIdx.x * 256 + threadIdx.x;
    int i1 = ((t & ~(j-1)) << 1) | (t & (j-1));
    int i2 = i1 + j;
    bool up = (((i1 & (NSORT-1)) & k) == 0);
    float ka = g_key[i1], kb = g_key[i2];
    int ia = g_idx[i1], ib = g_idx[i2];
    if (sbefore(ka, ia, kb, ib) != up) {
        g_key[i1] = kb; g_idx[i1] = ib; g_key[i2] = ka; g_idx[i2] = ia;
    }
}

__global__ __launch_bounds__(1024) void bitonic_merge_local(int k)
{
    __shared__ float sk[2048];
    __shared__ int   si[2048];
    int base = blockIdx.x * 2048;
    int t = threadIdx.x;
    sk[t] = g_key[base+t]; si[t] = g_idx[base+t];
    sk[t+1024] = g_key[base+t+1024]; si[t+1024] = g_idx[base+t+1024];
    __syncthreads();
    for (int j = 1024; j >= 1; j >>= 1) {
        int i1 = ((t & ~(j-1)) << 1) | (t & (j-1));
        int i2 = i1 + j;
        bool up = ((((base+i1) & (NSORT-1)) & k) == 0);
        float ka = sk[i1], kb = sk[i2];
        int ia = si[i1], ib = si[i2];
        if (sbefore(ka, ia, kb, ib) != up) {
            sk[i1] = kb; si[i1] = ib; sk[i2] = ka; si[i2] = ia;
        }
        __syncthreads();
    }
    g_key[base+t] = sk[t]; g_idx[base+t] = si[t];
    g_key[base+t+1024] = sk[t+1024]; g_idx[base+t+1024] = si[t+1024];
}

// ---------------- greedy NMS (exact, two-level chunked) + top-300 ----------------
__device__ __forceinline__ bool iou_gt(float ax1, float ay1, float ax2, float ay2, float aa,
                                       float bx1, float by1, float bx2, float by2, float ba)
{
    float ix1 = fmaxf(ax1, bx1);
    float iy1 = fmaxf(ay1, by1);
    float ix2 = fminf(ax2, bx2);
    float iy2 = fminf(ay2, by2);
    float inter = fmaxf(ix2 - ix1, 0.f) * fmaxf(iy2 - iy1, 0.f);
    float iou = inter / (aa + ba - inter + 1e-9f);
    return iou > 0.7f;
}

__global__ __launch_bounds__(1024) void nms_kernel(float* __restrict__ out)
{
    extern __shared__ float sm[];
    float* x1 = sm;
    float* y1 = sm + PRE;
    float* x2 = sm + 2*PRE;
    float* y2 = sm + 3*PRE;
    float* ar = sm + 4*PRE;
    unsigned char* keep = (unsigned char*)(sm + 5*PRE);
    __shared__ unsigned long long msk[64];
    __shared__ int kidx[64];
    __shared__ int kcnt;
    __shared__ int wsum[32];

    int n = blockIdx.x;
    int t = threadIdx.x;

    for (int i = t; i < PRE; i += 1024) {
        float k = g_key[n*NSORT + i];
        if (isfinite(k)) {
            int id = g_idx[n*NSORT + i];
            const float* r = g_roi + ((size_t)n*NA + id)*4;
            x1[i] = r[0]; y1[i] = r[1]; x2[i] = r[2]; y2[i] = r[3];
            ar[i] = (r[2]-r[0])*(r[3]-r[1]);
            keep[i] = 1;
        } else {
            x1[i] = y1[i] = x2[i] = y2[i] = ar[i] = 0.f;
            keep[i] = 0;
        }
    }
    for (int e = t; e < POST*4; e += 1024)
        out[OFF_ROIS + n*POST*4 + e] = 0.f;
    __syncthreads();

    for (int c0 = 0; c0 < PRE; c0 += 64) {
        int cend = c0 + 64 < PRE ? c0 + 64 : PRE;
        int cn = cend - c0;

        // phase 1a: per-box suppression masks within chunk (threads 0..63)
        if (t < 64) {
            unsigned long long m = 0ull;
            if (t < cn && keep[c0 + t]) {
                float bx1 = x1[c0+t], by1 = y1[c0+t], bx2 = x2[c0+t], by2 = y2[c0+t], ba = ar[c0+t];
                for (int k = t + 1; k < cn; ++k) {
                    if (iou_gt(bx1, by1, bx2, by2, ba,
                               x1[c0+k], y1[c0+k], x2[c0+k], y2[c0+k], ar[c0+k]))
                        m |= 1ull << k;
                }
            }
            msk[t] = m;
        }
        __syncthreads();

        // phase 1b: serial greedy resolve within chunk (warp 0, register dance)
        if (t < 32) {
            unsigned long long m0 = msk[t], m1 = msk[t + 32];
            unsigned b0 = __ballot_sync(0xffffffffu, (t < cn) && keep[c0 + t]);
            unsigned b1 = __ballot_sync(0xffffffffu, (t + 32 < cn) && keep[c0 + t + 32]);
            unsigned long long kmask = (unsigned long long)b0 | ((unsigned long long)b1 << 32);
            unsigned long long rm = 0ull, fk = 0ull;
            for (int k = 0; k < cn; ++k) {
                bool kp = ((kmask >> k) & 1ull) && !((rm >> k) & 1ull);
                if (kp) {
                    fk |= 1ull << k;
                    unsigned long long src = (k < 32) ? m0 : m1;
                    unsigned lo = __shfl_sync(0xffffffffu, (unsigned)src, k & 31);
                    unsigned hi = __shfl_sync(0xffffffffu, (unsigned)(src >> 32), k & 31);
                    rm |= ((unsigned long long)hi << 32) | lo;
                }
            }
            if (t < cn) {
                bool kp = (fk >> t) & 1ull;
                keep[c0 + t] = kp;
                if (kp) kidx[__popcll(fk & ((1ull << t) - 1ull))] = c0 + t;
            }
            if (t + 32 < cn) {
                bool kp = (fk >> (t + 32)) & 1ull;
                keep[c0 + t + 32] = kp;
                if (kp) kidx[__popcll(fk & ((1ull << (t + 32)) - 1ull))] = c0 + t + 32;
            }
            if (t == 0) kcnt = (int)__popcll(fk);
        }
        __syncthreads();

        // phase 2: apply chunk's kept boxes to all later boxes
        int kc = kcnt;
        if (kc > 0) {
            for (int j = cend + t; j < PRE; j += 1024) {
                if (keep[j]) {
                    float jx1 = x1[j], jy1 = y1[j], jx2 = x2[j], jy2 = y2[j], ja = ar[j];
                    for (int q = 0; q < kc; ++q) {
                        int i = kidx[q];
                        if (iou_gt(x1[i], y1[i], x2[i], y2[i], ar[i],
                                   jx1, jy1, jx2, jy2, ja)) { keep[j] = 0; break; }
                    }
                }
            }
        }
        __syncthreads();
    }

    // stable compaction: first POST kept boxes in score order
    int base_i = t * 6;
    int loc[6];
    int lsum = 0;
#pragma unroll
    for (int q = 0; q < 6; ++q) {
        int ii = base_i + q;
        int v = (ii < PRE) ? (int)keep[ii] : 0;
        loc[q] = lsum;
        lsum += v;
    }
    int lane = t & 31, wid = t >> 5;
    int v = lsum;
    for (int o = 1; o < 32; o <<= 1) {
        int u = __shfl_up_sync(0xffffffffu, v, o);
        if (lane >= o) v += u;
    }
    if (lane == 31) wsum[wid] = v;
    __syncthreads();
    if (wid == 0) {
        int w2 = wsum[lane];
        for (int o = 1; o < 32; o <<= 1) {
            int u = __shfl_up_sync(0xffffffffu, w2, o);
            if (lane >= o) w2 += u;
        }
        wsum[lane] = w2;
    }
    __syncthreads();
    int excl = v - lsum + (wid > 0 ? wsum[wid-1] : 0);
#pragma unroll
    for (int q = 0; q < 6; ++q) {
        int ii = base_i + q;
        if (ii < PRE && keep[ii]) {
            int r = excl + loc[q];
            if (r < POST) {
                float* o = out + OFF_ROIS + ((size_t)n*POST + r)*4;
                o[0] = x1[ii]; o[1] = y1[ii]; o[2] = x2[ii]; o[3] = y2[ii];
            }
        }
    }
}

// ---------------- launch ----------------
extern "C" void kernel_launch(void* const* d_in, const int* in_sizes, int n_in,
                              void* d_out, int out_size)
{
    const float* x   = (const float*)d_in[0];
    const float* w1  = (const float*)d_in[1];
    const float* bc  = (const float*)d_in[2];
    const float* sw  = (const float*)d_in[3];
    const float* sbb = (const float*)d_in[4];
    const float* lw  = (const float*)d_in[5];
    const float* lb  = (const float*)d_in[6];
    const void*  ih  = d_in[7];
    const void*  iw  = d_in[8];
    float* out = (float*)d_out;

    static bool attr_done = false;
    if (!attr_done) {
        cudaFuncSetAttribute(conv_mma_kernel, cudaFuncAttributeMaxDynamicSharedMemorySize, SMEM_CONV);
        cudaFuncSetAttribute(heads_kernel, cudaFuncAttributeMaxDynamicSharedMemorySize, 512*54*4);
        cudaFuncSetAttribute(nms_kernel, cudaFuncAttributeMaxDynamicSharedMemorySize, 131072);
        attr_done = true;
    }

    wcvt_kernel<<<(CO*KD + 255)/256, 256>>>(w1);
    im2col_kernel<<<dim3(16, 51, BATCH), 256>>>(x);
    anchors_kernel<<<(NA + 255)/256, 256>>>(out);
    conv_mma_kernel<<<dim3(CO/128, PPAD/64, BATCH), 256, SMEM_CONV>>>(bc);
    heads_kernel<<<dim3((P + 255)/256, BATCH), 256, 512*54*4>>>(sw, sbb, lw, lb, out);
    prep_kernel<<<(BATCH*NSORT)/256, 256>>>(out, ih, iw);

    bitonic_local<<<BATCH*NSORT/2048, 1024>>>();
    for (int k = 4096; k <= NSORT; k <<= 1) {
        for (int j = k >> 1; j >= 2048; j >>= 1)
            bitonic_global<<<(BATCH*NSORT/2)/256, 256>>>(j, k);
        bitonic_merge_local<<<BATCH*NSORT/2048, 1024>>>(k);
    }

    nms_kernel<<<BATCH, 1024, 5*PRE*4 + PRE>>>(out);
}